// round 11
// baseline (speedup 1.0000x reference)
#include <cuda_runtime.h>
#include <cstdint>

#define H_IMG 56
#define W_IMG 56
#define HW    3136
#define CIN   256
#define COUT  256
#define RANK  32
#define BATCH 16
#define PADD  58   // 58x58 halo-padded planes for T

typedef unsigned long long ull;

// Scratch: T[b][k][r][1+h][1+w], halo kept zero so stage-2 gather has no bounds checks.
__device__ float g_T[(size_t)BATCH * 9 * RANK * PADD * PADD];

// ---- packed f32x2 helpers ----------------------------------------------
__device__ __forceinline__ ull dup2(float v) {
    ull d; unsigned u = __float_as_uint(v);
    asm("mov.b64 %0, {%1, %1};" : "=l"(d) : "r"(u));
    return d;
}
__device__ __forceinline__ void fma2(ull& a, ull x, ull y) {
    asm("fma.rn.f32x2 %0, %1, %2, %0;" : "+l"(a) : "l"(x), "l"(y));
}
__device__ __forceinline__ float2 unpk(ull v) {
    unsigned lo, hi;
    asm("mov.b64 {%0, %1}, %2;" : "=r"(lo), "=r"(hi) : "l"(v));
    return make_float2(__uint_as_float(lo), __uint_as_float(hi));
}

// ---------------------------------------------------------------------------
// Stage 1: T[k] = G[k] @ x   (per-pixel projection to rank space)
// Per (k,b): M=32 (r), K=256 (c), N=3136 (pixels).
// Block: 224 threads, tile M=32 x N=448 (8 image rows), thread = 8r x 8p.
// ---------------------------------------------------------------------------
#define CT 16
__global__ __launch_bounds__(224) void lrconv_stage1(
    const float* __restrict__ x, const float* __restrict__ G)
{
    const int k  = blockIdx.y;
    const int b  = blockIdx.z;
    const int p0 = blockIdx.x * 448;            // 448 = 8*56, never crosses partial rows

    __shared__ __align__(16) float xs[CT][448];
    __shared__ __align__(16) float Gs[CT][36];  // padded: 144B row stride (16B-mult)

    const int tid = threadIdx.x;
    const int tx  = tid % 56;   // 56 pixel groups x 8 pixels
    const int ty  = tid / 56;   // 4 r groups x 8 r

    ull acc[8][4];
    #pragma unroll
    for (int j = 0; j < 8; j++)
        #pragma unroll
        for (int q = 0; q < 4; q++) acc[j][q] = 0ULL;

    const float* xb = x + (size_t)b * CIN * HW;
    const float* Gk = G + k * RANK * CIN;

    for (int c0 = 0; c0 < CIN; c0 += CT) {
        __syncthreads();
        // xs tile: 16 x 448 floats = 1792 float4, 8 per thread. Always in-bounds.
        #pragma unroll
        for (int i = 0; i < 8; i++) {
            int f4  = tid + i * 224;
            int row = f4 / 112;                 // 112 float4 per c-row
            int col = (f4 - row * 112) * 4;
            *(float4*)&xs[row][col] =
                *(const float4*)(xb + (size_t)(c0 + row) * HW + p0 + col);
        }
        // Gs tile: 16c x 32r, transposed to [c][r]
        #pragma unroll
        for (int i = 0; i < 3; i++) {
            int idx = tid + i * 224;
            if (idx < 512) {
                int c = idx & 15, r = idx >> 4;
                Gs[c][r] = Gk[r * CIN + c0 + c];
            }
        }
        __syncthreads();

        #pragma unroll 4
        for (int c = 0; c < CT; c++) {
            float4 g0 = *(const float4*)&Gs[c][ty * 8];
            float4 g1 = *(const float4*)&Gs[c][ty * 8 + 4];
            ull gd[8];
            gd[0] = dup2(g0.x); gd[1] = dup2(g0.y); gd[2] = dup2(g0.z); gd[3] = dup2(g0.w);
            gd[4] = dup2(g1.x); gd[5] = dup2(g1.y); gd[6] = dup2(g1.z); gd[7] = dup2(g1.w);
            ulonglong2 xv0 = *(const ulonglong2*)&xs[c][tx * 8];
            ulonglong2 xv1 = *(const ulonglong2*)&xs[c][tx * 8 + 4];
            ull xv[4] = { xv0.x, xv0.y, xv1.x, xv1.y };
            #pragma unroll
            for (int j = 0; j < 8; j++)
                #pragma unroll
                for (int q = 0; q < 4; q++)
                    fma2(acc[j][q], gd[j], xv[q]);
        }
    }

    // scatter into halo-padded T; each thread's 8 pixels are one contiguous row run
    const int pbase = p0 + tx * 8;
    const int hh = pbase / W_IMG;
    const int w0 = pbase - hh * W_IMG;
    #pragma unroll
    for (int j = 0; j < 8; j++) {
        int r = ty * 8 + j;
        float* dst = g_T + ((((size_t)b * 9 + k) * RANK + r) * PADD + (hh + 1)) * PADD + (w0 + 1);
        #pragma unroll
        for (int q = 0; q < 4; q++) {
            float2 v = unpk(acc[j][q]);
            dst[2 * q]     = v.x;
            dst[2 * q + 1] = v.y;
        }
    }
}

// ---------------------------------------------------------------------------
// Stage 2: out = (1/9) * sum_k Hm[k] @ shift_k(T[k]) + bias
// Block: 224 threads, one (b,h): o-tile 256 x w-tile 56, thread = 8o x 8w.
// Per tap: T slice staged into smem PRE-SHIFTED by kj -> all inner LDS aligned.
// ---------------------------------------------------------------------------
__global__ __launch_bounds__(224) void lrconv_stage2(
    const float* __restrict__ Hm, const float* __restrict__ bias,
    float* __restrict__ out)
{
    const int h = blockIdx.x;
    const int b = blockIdx.y;

    __shared__ __align__(16) float Hs[32][260];  // [r][o], 1040B stride (16B-mult)
    __shared__ __align__(16) float Ts[32][56];   // [r][w], pre-shifted by kj

    const int tid = threadIdx.x;
    const int tx  = tid % 7;    // 7 w groups x 8 w = 56
    const int ty  = tid / 7;    // 32 o groups x 8 o = 256

    ull acc[8][4];
    #pragma unroll
    for (int j = 0; j < 8; j++)
        #pragma unroll
        for (int q = 0; q < 4; q++) acc[j][q] = 0ULL;

    #pragma unroll 1
    for (int k = 0; k < 9; k++) {
        const int ki = k / 3;
        const int kj = k - ki * 3;
        __syncthreads();

        // Hm slab: Hm[k][o][r] -> Hs[r][o] (transposed), 2048 float4 loads
        #pragma unroll
        for (int i = 0; i < 10; i++) {
            int f4 = tid + i * 224;
            if (f4 < 2048) {
                int o  = f4 >> 3;
                int r4 = (f4 & 7) * 4;
                float4 v = *(const float4*)(Hm + ((size_t)k * COUT + o) * RANK + r4);
                Hs[r4 + 0][o] = v.x;
                Hs[r4 + 1][o] = v.y;
                Hs[r4 + 2][o] = v.z;
                Hs[r4 + 3][o] = v.w;
            }
        }
        // T slice: row (h+ki) of 32 rank planes, shifted left by kj. Always in-bounds
        // (x + kj <= 55 + 2 = 57 < 58).
        const float* Tp = g_T + ((((size_t)b * 9 + k) * RANK) * PADD + (h + ki)) * PADD + kj;
        #pragma unroll
        for (int i = 0; i < 8; i++) {
            int idx = tid + i * 224;      // 0..1791
            int r   = idx / 56;
            int xw  = idx - r * 56;
            Ts[r][xw] = Tp[(size_t)r * PADD * PADD + xw];
        }
        __syncthreads();

        #pragma unroll 4
        for (int r = 0; r < RANK; r++) {
            float4 h0 = *(const float4*)&Hs[r][ty * 8];
            float4 h1 = *(const float4*)&Hs[r][ty * 8 + 4];
            ull hd[8];
            hd[0] = dup2(h0.x); hd[1] = dup2(h0.y); hd[2] = dup2(h0.z); hd[3] = dup2(h0.w);
            hd[4] = dup2(h1.x); hd[5] = dup2(h1.y); hd[6] = dup2(h1.z); hd[7] = dup2(h1.w);
            ulonglong2 t0 = *(const ulonglong2*)&Ts[r][tx * 8];
            ulonglong2 t1 = *(const ulonglong2*)&Ts[r][tx * 8 + 4];
            ull tv[4] = { t0.x, t0.y, t1.x, t1.y };
            #pragma unroll
            for (int j = 0; j < 8; j++)
                #pragma unroll
                for (int q = 0; q < 4; q++)
                    fma2(acc[j][q], hd[j], tv[q]);
        }
    }

    const float inv9 = 1.f / 9.f;
    #pragma unroll
    for (int j = 0; j < 8; j++) {
        int o = ty * 8 + j;
        float bv = bias[o];
        float* dst = out + (((size_t)b * COUT + o) * H_IMG + h) * W_IMG + tx * 8;
        #pragma unroll
        for (int q = 0; q < 4; q++) {
            float2 v = unpk(acc[j][q]);
            dst[2 * q]     = v.x * inv9 + bv;
            dst[2 * q + 1] = v.y * inv9 + bv;
        }
    }
}

extern "C" void kernel_launch(void* const* d_in, const int* in_sizes, int n_in,
                              void* d_out, int out_size)
{
    const float* x    = (const float*)d_in[0];
    const float* G    = (const float*)d_in[1];
    const float* Hm   = (const float*)d_in[2];
    const float* bias = (const float*)d_in[3];
    float* out = (float*)d_out;

    void* tptr = nullptr;
    cudaGetSymbolAddress(&tptr, g_T);
    cudaMemsetAsync(tptr, 0, sizeof(g_T), 0);

    dim3 g1(HW / 448, 9, BATCH);      // (7, 9, 16)
    lrconv_stage1<<<g1, 224>>>(x, G);

    dim3 g2(H_IMG, BATCH);            // (56, 16)
    lrconv_stage2<<<g2, 224>>>(Hm, bias, out);
}

// round 12
// speedup vs baseline: 1.6292x; 1.6292x over previous
#include <cuda_runtime.h>
#include <cstdint>

#define H_IMG 56
#define W_IMG 56
#define HW    3136
#define CIN   256
#define COUT  256
#define RANK  32
#define BATCH 16
#define PADD  58   // 58x58 halo-padded planes for T

typedef unsigned long long ull;

// Scratch: T[b][k][r][1+h][1+w], halo kept zero so stage-2 gather has no bounds checks.
__device__ float g_T[(size_t)BATCH * 9 * RANK * PADD * PADD];

// ---- packed f32x2 helpers ----------------------------------------------
__device__ __forceinline__ ull dup2(float v) {
    ull d; unsigned u = __float_as_uint(v);
    asm("mov.b64 %0, {%1, %1};" : "=l"(d) : "r"(u));
    return d;
}
__device__ __forceinline__ void fma2(ull& a, ull x, ull y) {
    asm("fma.rn.f32x2 %0, %1, %2, %0;" : "+l"(a) : "l"(x), "l"(y));
}
__device__ __forceinline__ float2 unpk(ull v) {
    unsigned lo, hi;
    asm("mov.b64 {%0, %1}, %2;" : "=r"(lo), "=r"(hi) : "l"(v));
    return make_float2(__uint_as_float(lo), __uint_as_float(hi));
}

// ---------------------------------------------------------------------------
// Stage 1: T[k] = G[k] @ x   (per-pixel projection to rank space)
// Per (k,b): M=32 (r), K=256 (c), N=3136 (pixels).
// Block: 224 threads, tile M=32 x N=448 (8 image rows), thread = 8r x 8p.
// ---------------------------------------------------------------------------
#define CT 16
__global__ __launch_bounds__(224) void lrconv_stage1(
    const float* __restrict__ x, const float* __restrict__ G)
{
    const int k  = blockIdx.y;
    const int b  = blockIdx.z;
    const int p0 = blockIdx.x * 448;            // 448 = 8*56, never crosses partial rows

    __shared__ __align__(16) float xs[CT][448];
    __shared__ __align__(16) float Gs[CT][36];  // padded: 144B row stride (16B-mult)

    const int tid = threadIdx.x;
    const int tx  = tid % 56;   // 56 pixel groups x 8 pixels
    const int ty  = tid / 56;   // 4 r groups x 8 r

    ull acc[8][4];
    #pragma unroll
    for (int j = 0; j < 8; j++)
        #pragma unroll
        for (int q = 0; q < 4; q++) acc[j][q] = 0ULL;

    const float* xb = x + (size_t)b * CIN * HW;
    const float* Gk = G + k * RANK * CIN;

    for (int c0 = 0; c0 < CIN; c0 += CT) {
        __syncthreads();
        // xs tile: 16 x 448 floats = 1792 float4, 8 per thread. Always in-bounds.
        #pragma unroll
        for (int i = 0; i < 8; i++) {
            int f4  = tid + i * 224;
            int row = f4 / 112;                 // 112 float4 per c-row
            int col = (f4 - row * 112) * 4;
            *(float4*)&xs[row][col] =
                *(const float4*)(xb + (size_t)(c0 + row) * HW + p0 + col);
        }
        // Gs tile: 16c x 32r, transposed to [c][r]
        #pragma unroll
        for (int i = 0; i < 3; i++) {
            int idx = tid + i * 224;
            if (idx < 512) {
                int c = idx & 15, r = idx >> 4;
                Gs[c][r] = Gk[r * CIN + c0 + c];
            }
        }
        __syncthreads();

        #pragma unroll 4
        for (int c = 0; c < CT; c++) {
            float4 g0 = *(const float4*)&Gs[c][ty * 8];
            float4 g1 = *(const float4*)&Gs[c][ty * 8 + 4];
            ull gd[8];
            gd[0] = dup2(g0.x); gd[1] = dup2(g0.y); gd[2] = dup2(g0.z); gd[3] = dup2(g0.w);
            gd[4] = dup2(g1.x); gd[5] = dup2(g1.y); gd[6] = dup2(g1.z); gd[7] = dup2(g1.w);
            ulonglong2 xv0 = *(const ulonglong2*)&xs[c][tx * 8];
            ulonglong2 xv1 = *(const ulonglong2*)&xs[c][tx * 8 + 4];
            ull xv[4] = { xv0.x, xv0.y, xv1.x, xv1.y };
            #pragma unroll
            for (int j = 0; j < 8; j++)
                #pragma unroll
                for (int q = 0; q < 4; q++)
                    fma2(acc[j][q], gd[j], xv[q]);
        }
    }

    // scatter into halo-padded T; each thread's 8 pixels are one contiguous row run
    const int pbase = p0 + tx * 8;
    const int hh = pbase / W_IMG;
    const int w0 = pbase - hh * W_IMG;
    #pragma unroll
    for (int j = 0; j < 8; j++) {
        int r = ty * 8 + j;
        float* dst = g_T + ((((size_t)b * 9 + k) * RANK + r) * PADD + (hh + 1)) * PADD + (w0 + 1);
        #pragma unroll
        for (int q = 0; q < 4; q++) {
            float2 v = unpk(acc[j][q]);
            dst[2 * q]     = v.x;
            dst[2 * q + 1] = v.y;
        }
    }
}

// ---------------------------------------------------------------------------
// Stage 2: out = (1/9) * sum_k Hm[k] @ shift_k(T[k]) + bias
// Block: 224 threads, one (b,h): o-tile 256 x w-tile 56, thread = 8o x 8w.
// Per tap: T slice staged into smem PRE-SHIFTED by kj -> all inner LDS aligned.
// ---------------------------------------------------------------------------
__global__ __launch_bounds__(224) void lrconv_stage2(
    const float* __restrict__ Hm, const float* __restrict__ bias,
    float* __restrict__ out)
{
    const int h = blockIdx.x;
    const int b = blockIdx.y;

    __shared__ __align__(16) float Hs[32][260];  // [r][o], 1040B stride (16B-mult)
    __shared__ __align__(16) float Ts[32][56];   // [r][w], pre-shifted by kj

    const int tid = threadIdx.x;
    const int tx  = tid % 7;    // 7 w groups x 8 w = 56
    const int ty  = tid / 7;    // 32 o groups x 8 o = 256

    ull acc[8][4];
    #pragma unroll
    for (int j = 0; j < 8; j++)
        #pragma unroll
        for (int q = 0; q < 4; q++) acc[j][q] = 0ULL;

    #pragma unroll 1
    for (int k = 0; k < 9; k++) {
        const int ki = k / 3;
        const int kj = k - ki * 3;
        __syncthreads();

        // Hm slab: Hm[k][o][r] -> Hs[r][o] (transposed), 2048 float4 loads
        #pragma unroll
        for (int i = 0; i < 10; i++) {
            int f4 = tid + i * 224;
            if (f4 < 2048) {
                int o  = f4 >> 3;
                int r4 = (f4 & 7) * 4;
                float4 v = *(const float4*)(Hm + ((size_t)k * COUT + o) * RANK + r4);
                Hs[r4 + 0][o] = v.x;
                Hs[r4 + 1][o] = v.y;
                Hs[r4 + 2][o] = v.z;
                Hs[r4 + 3][o] = v.w;
            }
        }
        // T slice: row (h+ki) of 32 rank planes, shifted left by kj. Always in-bounds
        // (x + kj <= 55 + 2 = 57 < 58).
        const float* Tp = g_T + ((((size_t)b * 9 + k) * RANK) * PADD + (h + ki)) * PADD + kj;
        #pragma unroll
        for (int i = 0; i < 8; i++) {
            int idx = tid + i * 224;      // 0..1791
            int r   = idx / 56;
            int xw  = idx - r * 56;
            Ts[r][xw] = Tp[(size_t)r * PADD * PADD + xw];
        }
        __syncthreads();

        #pragma unroll 4
        for (int r = 0; r < RANK; r++) {
            float4 h0 = *(const float4*)&Hs[r][ty * 8];
            float4 h1 = *(const float4*)&Hs[r][ty * 8 + 4];
            ull hd[8];
            hd[0] = dup2(h0.x); hd[1] = dup2(h0.y); hd[2] = dup2(h0.z); hd[3] = dup2(h0.w);
            hd[4] = dup2(h1.x); hd[5] = dup2(h1.y); hd[6] = dup2(h1.z); hd[7] = dup2(h1.w);
            ulonglong2 t0 = *(const ulonglong2*)&Ts[r][tx * 8];
            ulonglong2 t1 = *(const ulonglong2*)&Ts[r][tx * 8 + 4];
            ull tv[4] = { t0.x, t0.y, t1.x, t1.y };
            #pragma unroll
            for (int j = 0; j < 8; j++)
                #pragma unroll
                for (int q = 0; q < 4; q++)
                    fma2(acc[j][q], hd[j], tv[q]);
        }
    }

    const float inv9 = 1.f / 9.f;
    #pragma unroll
    for (int j = 0; j < 8; j++) {
        int o = ty * 8 + j;
        float bv = bias[o];
        float* dst = out + (((size_t)b * COUT + o) * H_IMG + h) * W_IMG + tx * 8;
        #pragma unroll
        for (int q = 0; q < 4; q++) {
            float2 v = unpk(acc[j][q]);
            dst[2 * q]     = v.x * inv9 + bv;
            dst[2 * q + 1] = v.y * inv9 + bv;
        }
    }
}

extern "C" void kernel_launch(void* const* d_in, const int* in_sizes, int n_in,
                              void* d_out, int out_size)
{
    const float* x    = (const float*)d_in[0];
    const float* G    = (const float*)d_in[1];
    const float* Hm   = (const float*)d_in[2];
    const float* bias = (const float*)d_in[3];
    float* out = (float*)d_out;

    void* tptr = nullptr;
    cudaGetSymbolAddress(&tptr, g_T);
    cudaMemsetAsync(tptr, 0, sizeof(g_T), 0);

    dim3 g1(HW / 448, 9, BATCH);      // (7, 9, 16)
    lrconv_stage1<<<g1, 224>>>(x, G);

    dim3 g2(H_IMG, BATCH);            // (56, 16)
    lrconv_stage2<<<g2, 224>>>(Hm, bias, out);
}